// round 1
// baseline (speedup 1.0000x reference)
#include <cuda_runtime.h>

#define NNODES 50000
#define NEDGES 800000
#define CDIM   64
#define EPS_LN 1e-5f

typedef unsigned long long ull;

// ---------------- scratch (no allocations allowed) ----------------
__device__ float g_x[NNODES * CDIM];    // node features between layers
__device__ float g_e[(size_t)NEDGES * CDIM];  // edge features between layers
__device__ float g_agg[NNODES * CDIM];  // scatter-add accumulator

// ---------------- f32x2 helpers ----------------
__device__ __forceinline__ ull fma2(ull a, ull b, ull c) {
    ull d; asm("fma.rn.f32x2 %0, %1, %2, %3;" : "=l"(d) : "l"(a), "l"(b), "l"(c)); return d;
}
__device__ __forceinline__ ull dup2(float v) {
    ull d; asm("mov.b64 %0, {%1, %1};" : "=l"(d) : "f"(v)); return d;
}
__device__ __forceinline__ void unpack2(ull v, float& lo, float& hi) {
    asm("mov.b64 {%0, %1}, %2;" : "=f"(lo), "=f"(hi) : "l"(v));
}
__device__ __forceinline__ void red2(float* p, float a, float b) {
    asm volatile("red.global.add.v2.f32 [%0], {%1, %2};" :: "l"(p), "f"(a), "f"(b) : "memory");
}

// ================= EDGE KERNEL =================
// Shared layout (float offsets)
#define E_W0   0          // 192*64
#define E_W1   12288      // 64*64
#define E_W2   16384      // 64*64
#define E_B0   20480
#define E_B1   20544
#define E_B2   20608
#define E_G    20672
#define E_BT   20736
#define E_BUF  20800      // per-warp buffer: 1536 floats (768 float2)
#define E_BUF_WARP 1536
#define E_SMEM_FLOATS (E_BUF + 4 * E_BUF_WARP)   // 26944 floats = 107776 B

__global__ void __launch_bounds__(128) edge_kernel(
    const float* __restrict__ x, const float* __restrict__ ein, float* __restrict__ eout,
    const int* __restrict__ src, const int* __restrict__ dst,
    const float* __restrict__ W0, const float* __restrict__ b0,
    const float* __restrict__ W1, const float* __restrict__ b1,
    const float* __restrict__ W2, const float* __restrict__ b2,
    const float* __restrict__ gam, const float* __restrict__ bet)
{
    extern __shared__ float sm[];
    const int tid = threadIdx.x;
    for (int i = tid; i < 12288; i += 128) sm[E_W0 + i] = W0[i];
    for (int i = tid; i < 4096; i += 128) { sm[E_W1 + i] = W1[i]; sm[E_W2 + i] = W2[i]; }
    if (tid < 64) {
        sm[E_B0 + tid] = b0[tid]; sm[E_B1 + tid] = b1[tid]; sm[E_B2 + tid] = b2[tid];
        sm[E_G + tid]  = gam[tid]; sm[E_BT + tid] = bet[tid];
    }
    __syncthreads();

    const int warp = tid >> 5, lane = tid & 31;
    const int c0 = 2 * lane;
    float2* buf = (float2*)(sm + E_BUF + warp * E_BUF_WARP);
    const ull* bufu = (const ull*)buf;

    const ull bias0a = dup2(sm[E_B0 + c0]), bias0b = dup2(sm[E_B0 + c0 + 1]);
    const ull bias1a = dup2(sm[E_B1 + c0]), bias1b = dup2(sm[E_B1 + c0 + 1]);
    const ull bias2a = dup2(sm[E_B2 + c0]), bias2b = dup2(sm[E_B2 + c0 + 1]);
    const float gv0 = sm[E_G + c0], gv1 = sm[E_G + c0 + 1];
    const float bt0 = sm[E_BT + c0], bt1 = sm[E_BT + c0 + 1];

    const int nTiles = NEDGES / 8;
    for (int tile = blockIdx.x * 4 + warp; tile < nTiles; tile += gridDim.x * 4) {
        const int e0 = tile * 8;
        int das[4], dbs[4];
        // ---- gather inputs: buf[p*192 + k] = (inA[k], inB[k]) ----
        #pragma unroll
        for (int p = 0; p < 4; p++) {
            const int ea = e0 + 2 * p, eb = ea + 1;
            const int sa = src[ea], sb = src[eb];
            const int da = dst[ea], db = dst[eb];
            das[p] = da; dbs[p] = db;
            #pragma unroll
            for (int kk = 0; kk < 2; kk++) {
                const int k = lane + kk * 32;
                buf[p * 192 + k]       = make_float2(x[sa * CDIM + k], x[sb * CDIM + k]);
                buf[p * 192 + 64 + k]  = make_float2(x[da * CDIM + k], x[db * CDIM + k]);
                buf[p * 192 + 128 + k] = make_float2(ein[(size_t)ea * CDIM + k],
                                                     ein[(size_t)eb * CDIM + k]);
            }
        }
        __syncwarp();

        ull acc0[4], acc1[4];
        // ---- layer 1: 192 -> 64, relu ----
        #pragma unroll
        for (int p = 0; p < 4; p++) { acc0[p] = bias0a; acc1[p] = bias0b; }
        #pragma unroll 4
        for (int k = 0; k < 192; k++) {
            const float2 w = *(const float2*)&sm[E_W0 + k * 64 + c0];
            const ull wa = dup2(w.x), wb = dup2(w.y);
            #pragma unroll
            for (int p = 0; p < 4; p++) {
                const ull xp = bufu[p * 192 + k];
                acc0[p] = fma2(xp, wa, acc0[p]);
                acc1[p] = fma2(xp, wb, acc1[p]);
            }
        }
        __syncwarp();
        #pragma unroll
        for (int p = 0; p < 4; p++) {
            float l0, h0, l1, h1; unpack2(acc0[p], l0, h0); unpack2(acc1[p], l1, h1);
            float4 v; v.x = fmaxf(l0, 0.f); v.y = fmaxf(h0, 0.f);
            v.z = fmaxf(l1, 0.f); v.w = fmaxf(h1, 0.f);
            *(float4*)&buf[p * 64 + c0] = v;   // h1 in entries [0,256)
        }
        __syncwarp();

        // ---- layer 2: 64 -> 64, relu ----
        #pragma unroll
        for (int p = 0; p < 4; p++) { acc0[p] = bias1a; acc1[p] = bias1b; }
        #pragma unroll 4
        for (int k = 0; k < 64; k++) {
            const float2 w = *(const float2*)&sm[E_W1 + k * 64 + c0];
            const ull wa = dup2(w.x), wb = dup2(w.y);
            #pragma unroll
            for (int p = 0; p < 4; p++) {
                const ull xp = bufu[p * 64 + k];
                acc0[p] = fma2(xp, wa, acc0[p]);
                acc1[p] = fma2(xp, wb, acc1[p]);
            }
        }
        __syncwarp();
        #pragma unroll
        for (int p = 0; p < 4; p++) {
            float l0, h0, l1, h1; unpack2(acc0[p], l0, h0); unpack2(acc1[p], l1, h1);
            float4 v; v.x = fmaxf(l0, 0.f); v.y = fmaxf(h0, 0.f);
            v.z = fmaxf(l1, 0.f); v.w = fmaxf(h1, 0.f);
            *(float4*)&buf[256 + p * 64 + c0] = v;  // h2 in entries [256,512)
        }
        __syncwarp();

        // ---- layer 3: 64 -> 64 (no relu) ----
        #pragma unroll
        for (int p = 0; p < 4; p++) { acc0[p] = bias2a; acc1[p] = bias2b; }
        #pragma unroll 4
        for (int k = 0; k < 64; k++) {
            const float2 w = *(const float2*)&sm[E_W2 + k * 64 + c0];
            const ull wa = dup2(w.x), wb = dup2(w.y);
            #pragma unroll
            for (int p = 0; p < 4; p++) {
                const ull xp = bufu[256 + p * 64 + k];
                acc0[p] = fma2(xp, wa, acc0[p]);
                acc1[p] = fma2(xp, wb, acc1[p]);
            }
        }

        // ---- LayerNorm + residual + scatter ----
        #pragma unroll
        for (int p = 0; p < 4; p++) {
            const int ea = e0 + 2 * p, eb = ea + 1;
            float a0, b0v, a1, b1v;
            unpack2(acc0[p], a0, b0v);  // (edgeA ch c0, edgeB ch c0)
            unpack2(acc1[p], a1, b1v);
            float sA = a0 + a1, sB = b0v + b1v;
            float qA = a0 * a0 + a1 * a1, qB = b0v * b0v + b1v * b1v;
            #pragma unroll
            for (int o = 16; o > 0; o >>= 1) {
                sA += __shfl_xor_sync(0xffffffffu, sA, o);
                sB += __shfl_xor_sync(0xffffffffu, sB, o);
                qA += __shfl_xor_sync(0xffffffffu, qA, o);
                qB += __shfl_xor_sync(0xffffffffu, qB, o);
            }
            const float mA = sA * (1.f / 64.f), mB = sB * (1.f / 64.f);
            const float rA = rsqrtf(qA * (1.f / 64.f) - mA * mA + EPS_LN);
            const float rB = rsqrtf(qB * (1.f / 64.f) - mB * mB + EPS_LN);
            const float oA0 = (a0 - mA) * rA * gv0 + bt0;
            const float oA1 = (a1 - mA) * rA * gv1 + bt1;
            const float oB0 = (b0v - mB) * rB * gv0 + bt0;
            const float oB1 = (b1v - mB) * rB * gv1 + bt1;
            const float2 eoA = *(const float2*)&ein[(size_t)ea * CDIM + c0];
            const float2 eoB = *(const float2*)&ein[(size_t)eb * CDIM + c0];
            const float nA0 = eoA.x + oA0, nA1 = eoA.y + oA1;
            const float nB0 = eoB.x + oB0, nB1 = eoB.y + oB1;
            *(float2*)&eout[(size_t)ea * CDIM + c0] = make_float2(nA0, nA1);
            *(float2*)&eout[(size_t)eb * CDIM + c0] = make_float2(nB0, nB1);
            red2(&g_agg[das[p] * CDIM + c0], nA0, nA1);
            red2(&g_agg[dbs[p] * CDIM + c0], nB0, nB1);
        }
    }
}

// ================= NODE KERNEL =================
#define N_W0   0          // 128*64
#define N_W1   8192       // 64*64
#define N_W2   12288      // 64*64
#define N_B0   16384
#define N_B1   16448
#define N_B2   16512
#define N_G    16576
#define N_BT   16640
#define N_BUF  16704      // per-warp buffer: 1024 floats (512 float2)
#define N_BUF_WARP 1024
#define N_SMEM_FLOATS (N_BUF + 4 * N_BUF_WARP)   // 20800 floats = 83200 B

__global__ void __launch_bounds__(128) node_kernel(
    const float* __restrict__ xin, float* __restrict__ xout,
    const float* __restrict__ W0, const float* __restrict__ b0,
    const float* __restrict__ W1, const float* __restrict__ b1,
    const float* __restrict__ W2, const float* __restrict__ b2,
    const float* __restrict__ gam, const float* __restrict__ bet)
{
    extern __shared__ float sm[];
    const int tid = threadIdx.x;
    for (int i = tid; i < 8192; i += 128) sm[N_W0 + i] = W0[i];
    for (int i = tid; i < 4096; i += 128) { sm[N_W1 + i] = W1[i]; sm[N_W2 + i] = W2[i]; }
    if (tid < 64) {
        sm[N_B0 + tid] = b0[tid]; sm[N_B1 + tid] = b1[tid]; sm[N_B2 + tid] = b2[tid];
        sm[N_G + tid]  = gam[tid]; sm[N_BT + tid] = bet[tid];
    }
    __syncthreads();

    const int warp = tid >> 5, lane = tid & 31;
    const int c0 = 2 * lane;
    float2* buf = (float2*)(sm + N_BUF + warp * N_BUF_WARP);
    const ull* bufu = (const ull*)buf;

    const ull bias0a = dup2(sm[N_B0 + c0]), bias0b = dup2(sm[N_B0 + c0 + 1]);
    const ull bias1a = dup2(sm[N_B1 + c0]), bias1b = dup2(sm[N_B1 + c0 + 1]);
    const ull bias2a = dup2(sm[N_B2 + c0]), bias2b = dup2(sm[N_B2 + c0 + 1]);
    const float gv0 = sm[N_G + c0], gv1 = sm[N_G + c0 + 1];
    const float bt0 = sm[N_BT + c0], bt1 = sm[N_BT + c0 + 1];

    const int nTiles = NNODES / 8;
    for (int tile = blockIdx.x * 4 + warp; tile < nTiles; tile += gridDim.x * 4) {
        const int n0 = tile * 8;
        // ---- gather inputs: buf[p*128 + k] = (inA[k], inB[k]) ----
        #pragma unroll
        for (int p = 0; p < 4; p++) {
            const int na = n0 + 2 * p, nb = na + 1;
            #pragma unroll
            for (int kk = 0; kk < 2; kk++) {
                const int k = lane + kk * 32;
                buf[p * 128 + k]      = make_float2(xin[na * CDIM + k], xin[nb * CDIM + k]);
                buf[p * 128 + 64 + k] = make_float2(g_agg[na * CDIM + k], g_agg[nb * CDIM + k]);
            }
        }
        __syncwarp();

        ull acc0[4], acc1[4];
        // ---- layer 1: 128 -> 64, relu ----
        #pragma unroll
        for (int p = 0; p < 4; p++) { acc0[p] = bias0a; acc1[p] = bias0b; }
        #pragma unroll 4
        for (int k = 0; k < 128; k++) {
            const float2 w = *(const float2*)&sm[N_W0 + k * 64 + c0];
            const ull wa = dup2(w.x), wb = dup2(w.y);
            #pragma unroll
            for (int p = 0; p < 4; p++) {
                const ull xp = bufu[p * 128 + k];
                acc0[p] = fma2(xp, wa, acc0[p]);
                acc1[p] = fma2(xp, wb, acc1[p]);
            }
        }
        __syncwarp();
        #pragma unroll
        for (int p = 0; p < 4; p++) {
            float l0, h0, l1, h1; unpack2(acc0[p], l0, h0); unpack2(acc1[p], l1, h1);
            float4 v; v.x = fmaxf(l0, 0.f); v.y = fmaxf(h0, 0.f);
            v.z = fmaxf(l1, 0.f); v.w = fmaxf(h1, 0.f);
            *(float4*)&buf[p * 64 + c0] = v;
        }
        __syncwarp();

        // ---- layer 2: 64 -> 64, relu ----
        #pragma unroll
        for (int p = 0; p < 4; p++) { acc0[p] = bias1a; acc1[p] = bias1b; }
        #pragma unroll 4
        for (int k = 0; k < 64; k++) {
            const float2 w = *(const float2*)&sm[N_W1 + k * 64 + c0];
            const ull wa = dup2(w.x), wb = dup2(w.y);
            #pragma unroll
            for (int p = 0; p < 4; p++) {
                const ull xp = bufu[p * 64 + k];
                acc0[p] = fma2(xp, wa, acc0[p]);
                acc1[p] = fma2(xp, wb, acc1[p]);
            }
        }
        __syncwarp();
        #pragma unroll
        for (int p = 0; p < 4; p++) {
            float l0, h0, l1, h1; unpack2(acc0[p], l0, h0); unpack2(acc1[p], l1, h1);
            float4 v; v.x = fmaxf(l0, 0.f); v.y = fmaxf(h0, 0.f);
            v.z = fmaxf(l1, 0.f); v.w = fmaxf(h1, 0.f);
            *(float4*)&buf[256 + p * 64 + c0] = v;
        }
        __syncwarp();

        // ---- layer 3: 64 -> 64 (no relu) ----
        #pragma unroll
        for (int p = 0; p < 4; p++) { acc0[p] = bias2a; acc1[p] = bias2b; }
        #pragma unroll 4
        for (int k = 0; k < 64; k++) {
            const float2 w = *(const float2*)&sm[N_W2 + k * 64 + c0];
            const ull wa = dup2(w.x), wb = dup2(w.y);
            #pragma unroll
            for (int p = 0; p < 4; p++) {
                const ull xp = bufu[256 + p * 64 + k];
                acc0[p] = fma2(xp, wa, acc0[p]);
                acc1[p] = fma2(xp, wb, acc1[p]);
            }
        }

        // ---- LayerNorm + residual ----
        #pragma unroll
        for (int p = 0; p < 4; p++) {
            const int na = n0 + 2 * p, nb = na + 1;
            float a0, b0v, a1, b1v;
            unpack2(acc0[p], a0, b0v);
            unpack2(acc1[p], a1, b1v);
            float sA = a0 + a1, sB = b0v + b1v;
            float qA = a0 * a0 + a1 * a1, qB = b0v * b0v + b1v * b1v;
            #pragma unroll
            for (int o = 16; o > 0; o >>= 1) {
                sA += __shfl_xor_sync(0xffffffffu, sA, o);
                sB += __shfl_xor_sync(0xffffffffu, sB, o);
                qA += __shfl_xor_sync(0xffffffffu, qA, o);
                qB += __shfl_xor_sync(0xffffffffu, qB, o);
            }
            const float mA = sA * (1.f / 64.f), mB = sB * (1.f / 64.f);
            const float rA = rsqrtf(qA * (1.f / 64.f) - mA * mA + EPS_LN);
            const float rB = rsqrtf(qB * (1.f / 64.f) - mB * mB + EPS_LN);
            const float oA0 = (a0 - mA) * rA * gv0 + bt0;
            const float oA1 = (a1 - mA) * rA * gv1 + bt1;
            const float oB0 = (b0v - mB) * rB * gv0 + bt0;
            const float oB1 = (b1v - mB) * rB * gv1 + bt1;
            const float2 xoA = *(const float2*)&xin[na * CDIM + c0];
            const float2 xoB = *(const float2*)&xin[nb * CDIM + c0];
            *(float2*)&xout[na * CDIM + c0] = make_float2(xoA.x + oA0, xoA.y + oA1);
            *(float2*)&xout[nb * CDIM + c0] = make_float2(xoB.x + oB0, xoB.y + oB1);
        }
    }
}

// ================= zero the aggregation buffer =================
__global__ void zero_agg_kernel() {
    float4* p = (float4*)g_agg;
    const int n = NNODES * CDIM / 4;
    for (int i = blockIdx.x * blockDim.x + threadIdx.x; i < n; i += gridDim.x * blockDim.x)
        p[i] = make_float4(0.f, 0.f, 0.f, 0.f);
}

// ================= launcher =================
extern "C" void kernel_launch(void* const* d_in, const int* in_sizes, int n_in,
                              void* d_out, int out_size) {
    const float* x_in = (const float*)d_in[0];
    const float* e_in = (const float*)d_in[1];
    const int*   ei   = (const int*)d_in[2];
    const int* src = ei;
    const int* dst = ei + NEDGES;
    const float* ew0 = (const float*)d_in[3];  const float* eb0 = (const float*)d_in[4];
    const float* ew1 = (const float*)d_in[5];  const float* eb1 = (const float*)d_in[6];
    const float* ew2 = (const float*)d_in[7];  const float* eb2 = (const float*)d_in[8];
    const float* eg  = (const float*)d_in[9];  const float* ebt = (const float*)d_in[10];
    const float* nw0 = (const float*)d_in[11]; const float* nb0 = (const float*)d_in[12];
    const float* nw1 = (const float*)d_in[13]; const float* nb1 = (const float*)d_in[14];
    const float* nw2 = (const float*)d_in[15]; const float* nb2 = (const float*)d_in[16];
    const float* ng  = (const float*)d_in[17]; const float* nbt = (const float*)d_in[18];

    float* out_x = (float*)d_out;
    float* out_e = (float*)d_out + (size_t)NNODES * CDIM;

    float* dx; float* de;
    cudaGetSymbolAddress((void**)&dx, g_x);
    cudaGetSymbolAddress((void**)&de, g_e);

    cudaFuncSetAttribute(edge_kernel, cudaFuncAttributeMaxDynamicSharedMemorySize,
                         E_SMEM_FLOATS * 4);
    cudaFuncSetAttribute(node_kernel, cudaFuncAttributeMaxDynamicSharedMemorySize,
                         N_SMEM_FLOATS * 4);

    const int EW0S = 192 * 64, EWS = 64 * 64, NW0S = 128 * 64;
    const int GRID = 296;  // 2 blocks/SM x 148 SMs

    for (int i = 0; i < 3; i++) {
        const float* xi   = (i == 0) ? x_in : dx;
        const float* einp = (i == 0) ? e_in : de;
        float* eo = (i == 2) ? out_e : de;
        float* xo = (i == 2) ? out_x : dx;

        zero_agg_kernel<<<256, 256>>>();
        edge_kernel<<<GRID, 128, E_SMEM_FLOATS * 4>>>(
            xi, einp, eo, src, dst,
            ew0 + i * EW0S, eb0 + i * 64, ew1 + i * EWS, eb1 + i * 64,
            ew2 + i * EWS, eb2 + i * 64, eg + i * 64, ebt + i * 64);
        node_kernel<<<GRID, 128, N_SMEM_FLOATS * 4>>>(
            xi, xo,
            nw0 + i * NW0S, nb0 + i * 64, nw1 + i * EWS, nb1 + i * 64,
            nw2 + i * EWS, nb2 + i * 64, ng + i * 64, nbt + i * 64);
    }
}